// round 8
// baseline (speedup 1.0000x reference)
#include <cuda_runtime.h>
#include <cstdint>

// ---------------- problem constants ----------------
#define BATCH   8
#define NQ      4096
#define NK      77
#define QDIM    1280
#define CDIM    768
#define HEADS   8
#define DHEAD   160
#define INNER   1280
#define SCALE_F 0.07905694150420949f   // 160^-0.5

// ---------------- scratch (device globals; no allocation allowed) ----------------
__device__ float g_Q[(size_t)BATCH * NQ * INNER];   // 167.8 MB
__device__ float g_K[(size_t)BATCH * NK * INNER];
__device__ float g_V[(size_t)BATCH * NK * INNER];
__device__ float g_A[(size_t)BATCH * NQ * INNER];   // 167.8 MB

// ---------------- small PTX helpers ----------------
__device__ __forceinline__ uint32_t f2tf32(float f) {
    uint32_t u;
    asm("cvt.rna.tf32.f32 %0, %1;" : "=r"(u) : "f"(f));
    return u;
}

__device__ __forceinline__ void cp16(void* smem, const void* gmem) {
    uint32_t s = (uint32_t)__cvta_generic_to_shared(smem);
    asm volatile("cp.async.cg.shared.global [%0], [%1], 16;" :: "r"(s), "l"(gmem));
}
__device__ __forceinline__ void cp_commit() { asm volatile("cp.async.commit_group;"); }
__device__ __forceinline__ void cp_wait0()  { asm volatile("cp.async.wait_group 0;"); }

__device__ __forceinline__ void mma_tf32(float (&c)[4],
                                         uint32_t a0, uint32_t a1, uint32_t a2, uint32_t a3,
                                         uint32_t b0, uint32_t b1) {
    asm volatile(
        "mma.sync.aligned.m16n8k8.row.col.f32.tf32.tf32.f32 "
        "{%0,%1,%2,%3}, {%4,%5,%6,%7}, {%8,%9}, {%0,%1,%2,%3};"
        : "+f"(c[0]), "+f"(c[1]), "+f"(c[2]), "+f"(c[3])
        : "r"(a0), "r"(a1), "r"(a2), "r"(a3), "r"(b0), "r"(b1));
}

// ---------------- generic tf32 GEMM: C[M,N] = A[M,K] @ B[K,N] (+bias) ----------------
// A row-major, B row-major ([in,out] weight layout). K % 16 == 0, N % 128 == 0.
#define BM 128
#define BN 128
#define BKT 16
#define LDA 20     // As row stride (floats): [BM][LDA]  -> conflict-free frag loads
#define LDB 132    // Bs row stride (floats): [BKT][LDB]

__global__ __launch_bounds__(256)
void gemm_tf32(const float* __restrict__ A, const float* __restrict__ Bm,
               const float* __restrict__ bias, float* __restrict__ C,
               int M, int N, int K)
{
    __shared__ __align__(16) float As[2][BM * LDA];
    __shared__ __align__(16) float Bs[2][BKT * LDB];

    const int tid  = threadIdx.x;
    const int bm   = blockIdx.y * BM;
    const int bn   = blockIdx.x * BN;
    const int warp = tid >> 5, lane = tid & 31;
    const int wm   = (warp & 1) * 64;     // warp M offset (2 warps along M)
    const int wn   = (warp >> 1) * 32;    // warp N offset (4 warps along N)
    const int g    = lane >> 2, tg = lane & 3;

    float acc[4][4][4];
#pragma unroll
    for (int i = 0; i < 4; i++)
#pragma unroll
        for (int j = 0; j < 4; j++)
#pragma unroll
            for (int k = 0; k < 4; k++) acc[i][j][k] = 0.f;

    const int T = K / BKT;

    // per-thread load coordinates (512 float4 per tile per matrix, 2 each)
    const int arow0 = tid >> 2;              // A: row = idx/4, k4 = idx%4
    const int ak0   = (tid & 3) * 4;
    const int arow1 = (tid + 256) >> 2;
    const int bk0   = tid >> 5;              // B: k = idx/32, n4 = idx%32
    const int bn0   = (tid & 31) * 4;
    const int bk1   = bk0 + 8;

    auto load_tile = [&](int t, int buf) {
        const int k0 = t * BKT;
        const float4 z = make_float4(0.f, 0.f, 0.f, 0.f);
        float* d0 = &As[buf][arow0 * LDA + ak0];
        if (bm + arow0 < M) cp16(d0, A + (size_t)(bm + arow0) * K + k0 + ak0);
        else                *(float4*)d0 = z;
        float* d1 = &As[buf][arow1 * LDA + ak0];
        if (bm + arow1 < M) cp16(d1, A + (size_t)(bm + arow1) * K + k0 + ak0);
        else                *(float4*)d1 = z;
        cp16(&Bs[buf][bk0 * LDB + bn0], Bm + (size_t)(k0 + bk0) * N + bn + bn0);
        cp16(&Bs[buf][bk1 * LDB + bn0], Bm + (size_t)(k0 + bk1) * N + bn + bn0);
    };

    load_tile(0, 0);
    cp_commit();

    for (int t = 0; t < T; t++) {
        cp_wait0();
        __syncthreads();
        const int buf = t & 1;
        if (t + 1 < T) { load_tile(t + 1, buf ^ 1); cp_commit(); }

#pragma unroll
        for (int kk = 0; kk < BKT; kk += 8) {
            uint32_t af[4][4], bf[4][2];
#pragma unroll
            for (int mi = 0; mi < 4; mi++) {
                const float* as = &As[buf][(wm + mi * 16) * LDA + kk];
                af[mi][0] = f2tf32(as[(g    ) * LDA + tg    ]);
                af[mi][1] = f2tf32(as[(g + 8) * LDA + tg    ]);
                af[mi][2] = f2tf32(as[(g    ) * LDA + tg + 4]);
                af[mi][3] = f2tf32(as[(g + 8) * LDA + tg + 4]);
            }
#pragma unroll
            for (int ni = 0; ni < 4; ni++) {
                const float* bs = &Bs[buf][kk * LDB + wn + ni * 8 + g];
                bf[ni][0] = f2tf32(bs[(size_t)tg * LDB]);
                bf[ni][1] = f2tf32(bs[(size_t)(tg + 4) * LDB]);
            }
#pragma unroll
            for (int mi = 0; mi < 4; mi++)
#pragma unroll
                for (int ni = 0; ni < 4; ni++)
                    mma_tf32(acc[mi][ni], af[mi][0], af[mi][1], af[mi][2], af[mi][3],
                             bf[ni][0], bf[ni][1]);
        }
        __syncthreads();
    }

    // epilogue: c0/c1 -> (row g, cols 2tg,2tg+1); c2/c3 -> row g+8
#pragma unroll
    for (int mi = 0; mi < 4; mi++) {
        const int r0 = bm + wm + mi * 16 + g;
        const int r1 = r0 + 8;
#pragma unroll
        for (int ni = 0; ni < 4; ni++) {
            const int n = bn + wn + ni * 8 + 2 * tg;
            float b0 = 0.f, b1 = 0.f;
            if (bias) { b0 = __ldg(bias + n); b1 = __ldg(bias + n + 1); }
            if (r0 < M) {
                float2 v = make_float2(acc[mi][ni][0] + b0, acc[mi][ni][1] + b1);
                *(float2*)(C + (size_t)r0 * N + n) = v;
            }
            if (r1 < M) {
                float2 v = make_float2(acc[mi][ni][2] + b0, acc[mi][ni][3] + b1);
                *(float2*)(C + (size_t)r1 * N + n) = v;
            }
        }
    }
}

// ---------------- attention: per-(b,h), Nk=77 fits in SMEM ----------------
// grid (32, H, B), 128 threads; one query row per thread; dyn smem = K+V tiles (98560 B)
__global__ __launch_bounds__(128)
void attn_kernel(const float* __restrict__ Q, const float* __restrict__ K,
                 const float* __restrict__ V, float* __restrict__ O)
{
    extern __shared__ __align__(16) float smem[];
    float4* Ks = (float4*)smem;                 // [77*40]
    float4* Vs = ((float4*)smem) + NK * 40;     // [77*40]

    const int tid = threadIdx.x;
    const int h = blockIdx.y, b = blockIdx.z;

    const float4* kg = (const float4*)(K + ((size_t)b * NK) * INNER + h * DHEAD);
    const float4* vg = (const float4*)(V + ((size_t)b * NK) * INNER + h * DHEAD);
    for (int i = tid; i < NK * 40; i += 128) {
        int r = i / 40, c = i - r * 40;
        Ks[i] = kg[(size_t)r * (INNER / 4) + c];
        Vs[i] = vg[(size_t)r * (INNER / 4) + c];
    }
    __syncthreads();

    const int row = blockIdx.x * 128 + tid;
    const float4* q = (const float4*)(Q + ((size_t)b * NQ + row) * INNER + h * DHEAD);

    float s[NK];
#pragma unroll
    for (int j = 0; j < NK; j++) s[j] = 0.f;

    for (int c = 0; c < 40; c++) {               // Dh/4 chunks
        float4 qv = __ldg(q + c);
#pragma unroll
        for (int j = 0; j < NK; j++) {
            float4 kv = Ks[j * 40 + c];          // broadcast LDS.128
            s[j] += qv.x * kv.x + qv.y * kv.y + qv.z * kv.z + qv.w * kv.w;
        }
    }

    float mx = s[0];
#pragma unroll
    for (int j = 1; j < NK; j++) mx = fmaxf(mx, s[j]);
    float l = 0.f;
#pragma unroll
    for (int j = 0; j < NK; j++) {
        float p = __expf((s[j] - mx) * SCALE_F);
        s[j] = p; l += p;
    }
    const float inv = 1.f / l;

    float4* op = (float4*)(O + ((size_t)b * NQ + row) * INNER + h * DHEAD);
    for (int c = 0; c < 40; c++) {
        float4 a = make_float4(0.f, 0.f, 0.f, 0.f);
#pragma unroll
        for (int j = 0; j < NK; j++) {
            float4 vv = Vs[j * 40 + c];          // broadcast LDS.128
            a.x += s[j] * vv.x; a.y += s[j] * vv.y;
            a.z += s[j] * vv.z; a.w += s[j] * vv.w;
        }
        a.x *= inv; a.y *= inv; a.z *= inv; a.w *= inv;
        op[c] = a;
    }
}

// ---------------- launch ----------------
extern "C" void kernel_launch(void* const* d_in, const int* in_sizes, int n_in,
                              void* d_out, int out_size)
{
    const float* x   = (const float*)d_in[0];   // [8,4096,1280]
    const float* ctx = (const float*)d_in[1];   // [8,77,768]
    const float* Wq  = (const float*)d_in[2];   // [1280,1280]
    const float* Wk  = (const float*)d_in[3];   // [768,1280]
    const float* Wv  = (const float*)d_in[4];   // [768,1280]
    const float* Wo  = (const float*)d_in[5];   // [1280,1280]
    const float* bo  = (const float*)d_in[6];   // [1280]
    float* out = (float*)d_out;

    void *pQ, *pK, *pV, *pA;
    cudaGetSymbolAddress(&pQ, g_Q);
    cudaGetSymbolAddress(&pK, g_K);
    cudaGetSymbolAddress(&pV, g_V);
    cudaGetSymbolAddress(&pA, g_A);

    const int Mq = BATCH * NQ;          // 32768
    const int Mk = BATCH * NK;          // 616

    // Q = x @ Wq
    gemm_tf32<<<dim3(INNER / BN, Mq / BM), 256>>>(x, Wq, nullptr, (float*)pQ, Mq, INNER, QDIM);
    // K = ctx @ Wk ; V = ctx @ Wv
    gemm_tf32<<<dim3(INNER / BN, (Mk + BM - 1) / BM), 256>>>(ctx, Wk, nullptr, (float*)pK, Mk, INNER, CDIM);
    gemm_tf32<<<dim3(INNER / BN, (Mk + BM - 1) / BM), 256>>>(ctx, Wv, nullptr, (float*)pV, Mk, INNER, CDIM);

    // attention
    const int attn_smem = 2 * NK * DHEAD * (int)sizeof(float);   // 98560 B
    cudaFuncSetAttribute(attn_kernel, cudaFuncAttributeMaxDynamicSharedMemorySize, attn_smem);
    attn_kernel<<<dim3(NQ / 128, HEADS, BATCH), 128, attn_smem>>>(
        (const float*)pQ, (const float*)pK, (const float*)pV, (float*)pA);

    // out = attn @ Wo + bo
    gemm_tf32<<<dim3(INNER / BN, Mq / BM), 256>>>((const float*)pA, Wo, bo, out, Mq, INNER, INNER);
}

// round 9
// speedup vs baseline: 1.0020x; 1.0020x over previous
#include <cuda_runtime.h>
#include <cstdint>

// ---------------- problem constants ----------------
#define BATCH   8
#define NQ      4096
#define NK      77
#define QDIM    1280
#define CDIM    768
#define HEADS   8
#define DHEAD   160
#define INNER   1280
#define SCALE_F 0.07905694150420949f   // 160^-0.5

// ---------------- scratch (device globals; no allocation allowed) ----------------
__device__ float g_Q[(size_t)BATCH * NQ * INNER];   // 167.8 MB
__device__ float g_K[(size_t)BATCH * NK * INNER];
__device__ float g_V[(size_t)BATCH * NK * INNER];
__device__ float g_A[(size_t)BATCH * NQ * INNER];   // 167.8 MB

// ---------------- small PTX helpers ----------------
__device__ __forceinline__ uint32_t f2tf32(float f) {
    uint32_t u;
    asm("cvt.rna.tf32.f32 %0, %1;" : "=r"(u) : "f"(f));
    return u;
}

__device__ __forceinline__ void cp16(void* smem, const void* gmem) {
    uint32_t s = (uint32_t)__cvta_generic_to_shared(smem);
    asm volatile("cp.async.cg.shared.global [%0], [%1], 16;" :: "r"(s), "l"(gmem));
}
__device__ __forceinline__ void cp_commit() { asm volatile("cp.async.commit_group;"); }
__device__ __forceinline__ void cp_wait0()  { asm volatile("cp.async.wait_group 0;"); }

__device__ __forceinline__ void mma_tf32(float (&c)[4],
                                         uint32_t a0, uint32_t a1, uint32_t a2, uint32_t a3,
                                         uint32_t b0, uint32_t b1) {
    asm volatile(
        "mma.sync.aligned.m16n8k8.row.col.f32.tf32.tf32.f32 "
        "{%0,%1,%2,%3}, {%4,%5,%6,%7}, {%8,%9}, {%0,%1,%2,%3};"
        : "+f"(c[0]), "+f"(c[1]), "+f"(c[2]), "+f"(c[3])
        : "r"(a0), "r"(a1), "r"(a2), "r"(a3), "r"(b0), "r"(b1));
}

// ---------------- generic tf32 GEMM: C[M,N] = A[M,K] @ B[K,N] (+bias) ----------------
// A row-major, B row-major ([in,out] weight layout). K % 16 == 0, N % 128 == 0.
#define BM 128
#define BN 128
#define BKT 16
#define LDA 20     // As row stride (floats): [BM][LDA]  -> conflict-free frag loads
#define LDB 132    // Bs row stride (floats): [BKT][LDB]

__global__ __launch_bounds__(256)
void gemm_tf32(const float* __restrict__ A, const float* __restrict__ Bm,
               const float* __restrict__ bias, float* __restrict__ C,
               int M, int N, int K)
{
    __shared__ __align__(16) float As[2][BM * LDA];
    __shared__ __align__(16) float Bs[2][BKT * LDB];

    const int tid  = threadIdx.x;
    const int bm   = blockIdx.y * BM;
    const int bn   = blockIdx.x * BN;
    const int warp = tid >> 5, lane = tid & 31;
    const int wm   = (warp & 1) * 64;     // warp M offset (2 warps along M)
    const int wn   = (warp >> 1) * 32;    // warp N offset (4 warps along N)
    const int g    = lane >> 2, tg = lane & 3;

    float acc[4][4][4];
#pragma unroll
    for (int i = 0; i < 4; i++)
#pragma unroll
        for (int j = 0; j < 4; j++)
#pragma unroll
            for (int k = 0; k < 4; k++) acc[i][j][k] = 0.f;

    const int T = K / BKT;

    // per-thread load coordinates (512 float4 per tile per matrix, 2 each)
    const int arow0 = tid >> 2;              // A: row = idx/4, k4 = idx%4
    const int ak0   = (tid & 3) * 4;
    const int arow1 = (tid + 256) >> 2;
    const int bk0   = tid >> 5;              // B: k = idx/32, n4 = idx%32
    const int bn0   = (tid & 31) * 4;
    const int bk1   = bk0 + 8;

    auto load_tile = [&](int t, int buf) {
        const int k0 = t * BKT;
        const float4 z = make_float4(0.f, 0.f, 0.f, 0.f);
        float* d0 = &As[buf][arow0 * LDA + ak0];
        if (bm + arow0 < M) cp16(d0, A + (size_t)(bm + arow0) * K + k0 + ak0);
        else                *(float4*)d0 = z;
        float* d1 = &As[buf][arow1 * LDA + ak0];
        if (bm + arow1 < M) cp16(d1, A + (size_t)(bm + arow1) * K + k0 + ak0);
        else                *(float4*)d1 = z;
        cp16(&Bs[buf][bk0 * LDB + bn0], Bm + (size_t)(k0 + bk0) * N + bn + bn0);
        cp16(&Bs[buf][bk1 * LDB + bn0], Bm + (size_t)(k0 + bk1) * N + bn + bn0);
    };

    load_tile(0, 0);
    cp_commit();

    for (int t = 0; t < T; t++) {
        cp_wait0();
        __syncthreads();
        const int buf = t & 1;
        if (t + 1 < T) { load_tile(t + 1, buf ^ 1); cp_commit(); }

#pragma unroll
        for (int kk = 0; kk < BKT; kk += 8) {
            uint32_t af[4][4], bf[4][2];
#pragma unroll
            for (int mi = 0; mi < 4; mi++) {
                const float* as = &As[buf][(wm + mi * 16) * LDA + kk];
                af[mi][0] = f2tf32(as[(g    ) * LDA + tg    ]);
                af[mi][1] = f2tf32(as[(g + 8) * LDA + tg    ]);
                af[mi][2] = f2tf32(as[(g    ) * LDA + tg + 4]);
                af[mi][3] = f2tf32(as[(g + 8) * LDA + tg + 4]);
            }
#pragma unroll
            for (int ni = 0; ni < 4; ni++) {
                const float* bs = &Bs[buf][kk * LDB + wn + ni * 8 + g];
                bf[ni][0] = f2tf32(bs[(size_t)tg * LDB]);
                bf[ni][1] = f2tf32(bs[(size_t)(tg + 4) * LDB]);
            }
#pragma unroll
            for (int mi = 0; mi < 4; mi++)
#pragma unroll
                for (int ni = 0; ni < 4; ni++)
                    mma_tf32(acc[mi][ni], af[mi][0], af[mi][1], af[mi][2], af[mi][3],
                             bf[ni][0], bf[ni][1]);
        }
        __syncthreads();
    }

    // epilogue: c0/c1 -> (row g, cols 2tg,2tg+1); c2/c3 -> row g+8
#pragma unroll
    for (int mi = 0; mi < 4; mi++) {
        const int r0 = bm + wm + mi * 16 + g;
        const int r1 = r0 + 8;
#pragma unroll
        for (int ni = 0; ni < 4; ni++) {
            const int n = bn + wn + ni * 8 + 2 * tg;
            float b0 = 0.f, b1 = 0.f;
            if (bias) { b0 = __ldg(bias + n); b1 = __ldg(bias + n + 1); }
            if (r0 < M) {
                float2 v = make_float2(acc[mi][ni][0] + b0, acc[mi][ni][1] + b1);
                *(float2*)(C + (size_t)r0 * N + n) = v;
            }
            if (r1 < M) {
                float2 v = make_float2(acc[mi][ni][2] + b0, acc[mi][ni][3] + b1);
                *(float2*)(C + (size_t)r1 * N + n) = v;
            }
        }
    }
}

// ---------------- attention: per-(b,h), Nk=77 fits in SMEM ----------------
// grid (32, H, B), 128 threads; one query row per thread; dyn smem = K+V tiles (98560 B)
__global__ __launch_bounds__(128)
void attn_kernel(const float* __restrict__ Q, const float* __restrict__ K,
                 const float* __restrict__ V, float* __restrict__ O)
{
    extern __shared__ __align__(16) float smem[];
    float4* Ks = (float4*)smem;                 // [77*40]
    float4* Vs = ((float4*)smem) + NK * 40;     // [77*40]

    const int tid = threadIdx.x;
    const int h = blockIdx.y, b = blockIdx.z;

    const float4* kg = (const float4*)(K + ((size_t)b * NK) * INNER + h * DHEAD);
    const float4* vg = (const float4*)(V + ((size_t)b * NK) * INNER + h * DHEAD);
    for (int i = tid; i < NK * 40; i += 128) {
        int r = i / 40, c = i - r * 40;
        Ks[i] = kg[(size_t)r * (INNER / 4) + c];
        Vs[i] = vg[(size_t)r * (INNER / 4) + c];
    }
    __syncthreads();

    const int row = blockIdx.x * 128 + tid;
    const float4* q = (const float4*)(Q + ((size_t)b * NQ + row) * INNER + h * DHEAD);

    float s[NK];
#pragma unroll
    for (int j = 0; j < NK; j++) s[j] = 0.f;

    for (int c = 0; c < 40; c++) {               // Dh/4 chunks
        float4 qv = __ldg(q + c);
#pragma unroll
        for (int j = 0; j < NK; j++) {
            float4 kv = Ks[j * 40 + c];          // broadcast LDS.128
            s[j] += qv.x * kv.x + qv.y * kv.y + qv.z * kv.z + qv.w * kv.w;
        }
    }

    float mx = s[0];
#pragma unroll
    for (int j = 1; j < NK; j++) mx = fmaxf(mx, s[j]);
    float l = 0.f;
#pragma unroll
    for (int j = 0; j < NK; j++) {
        float p = __expf((s[j] - mx) * SCALE_F);
        s[j] = p; l += p;
    }
    const float inv = 1.f / l;

    float4* op = (float4*)(O + ((size_t)b * NQ + row) * INNER + h * DHEAD);
    for (int c = 0; c < 40; c++) {
        float4 a = make_float4(0.f, 0.f, 0.f, 0.f);
#pragma unroll
        for (int j = 0; j < NK; j++) {
            float4 vv = Vs[j * 40 + c];          // broadcast LDS.128
            a.x += s[j] * vv.x; a.y += s[j] * vv.y;
            a.z += s[j] * vv.z; a.w += s[j] * vv.w;
        }
        a.x *= inv; a.y *= inv; a.z *= inv; a.w *= inv;
        op[c] = a;
    }
}

// ---------------- launch ----------------
extern "C" void kernel_launch(void* const* d_in, const int* in_sizes, int n_in,
                              void* d_out, int out_size)
{
    const float* x   = (const float*)d_in[0];   // [8,4096,1280]
    const float* ctx = (const float*)d_in[1];   // [8,77,768]
    const float* Wq  = (const float*)d_in[2];   // [1280,1280]
    const float* Wk  = (const float*)d_in[3];   // [768,1280]
    const float* Wv  = (const float*)d_in[4];   // [768,1280]
    const float* Wo  = (const float*)d_in[5];   // [1280,1280]
    const float* bo  = (const float*)d_in[6];   // [1280]
    float* out = (float*)d_out;

    void *pQ, *pK, *pV, *pA;
    cudaGetSymbolAddress(&pQ, g_Q);
    cudaGetSymbolAddress(&pK, g_K);
    cudaGetSymbolAddress(&pV, g_V);
    cudaGetSymbolAddress(&pA, g_A);

    const int Mq = BATCH * NQ;          // 32768
    const int Mk = BATCH * NK;          // 616

    // Q = x @ Wq
    gemm_tf32<<<dim3(INNER / BN, Mq / BM), 256>>>(x, Wq, nullptr, (float*)pQ, Mq, INNER, QDIM);
    // K = ctx @ Wk ; V = ctx @ Wv
    gemm_tf32<<<dim3(INNER / BN, (Mk + BM - 1) / BM), 256>>>(ctx, Wk, nullptr, (float*)pK, Mk, INNER, CDIM);
    gemm_tf32<<<dim3(INNER / BN, (Mk + BM - 1) / BM), 256>>>(ctx, Wv, nullptr, (float*)pV, Mk, INNER, CDIM);

    // attention
    const int attn_smem = 2 * NK * DHEAD * (int)sizeof(float);   // 98560 B
    cudaFuncSetAttribute(attn_kernel, cudaFuncAttributeMaxDynamicSharedMemorySize, attn_smem);
    attn_kernel<<<dim3(NQ / 128, HEADS, BATCH), 128, attn_smem>>>(
        (const float*)pQ, (const float*)pK, (const float*)pV, (float*)pA);

    // out = attn @ Wo + bo
    gemm_tf32<<<dim3(INNER / BN, Mq / BM), 256>>>((const float*)pA, Wo, bo, out, Mq, INNER, INNER);
}